// round 16
// baseline (speedup 1.0000x reference)
#include <cuda_runtime.h>
#include <cuda_fp16.h>
#include <math.h>
#include <stdint.h>

#define VOCAB   32000
#define EMBED   512
#define HIDDEN  1024
#define G4      4096
#define BATCH   64
#define SRCLEN  1024
#define NCTA    128

// Scratch (device globals)
__device__ __half   d_xp16[(size_t)SRCLEN * BATCH * G4];    // (t,b,g) fp16
__device__ __half   d_emb16[(size_t)VOCAB * EMBED];
// Wx in mma-B-fragment layout (R15, proven):
//   word(n, kt, tg, j) = (n>>3)*2048 + kt*64 + (n&7)*8 + tg*2 + j
__device__ unsigned d_wxf[(size_t)(G4 / 8) * 2048];
// Gathered embeddings in mma-A-fragment layout (R9-verified):
//   per 64-row block: word = kt*512 + (r&7)*64 + tg*16 + (r>>3)*2 + j
//   consumer uint4 at [kt*512 + g*64 + tg*16 + 4*mt] -> af = {x, z, y, w}
#define AB_WORDS 16384
__device__ unsigned d_af[(size_t)1024 * AB_WORDS];          // 64 MB
// h as half2 words in mma-A-fragment layout (R8):
//   word(kt, row, tg, j) = kt*512 + row*8 + tg*2 + j
__device__ unsigned d_hf[2][64 * 512];
// arrival counters: bar8[t*8 + (cta>>4)] -> 16; counters 2q,2q+1 = K-quarter q
__device__ unsigned d_bar8[SRCLEN * 8];

// ---------------------------------------------------------------------------
__device__ __forceinline__ void mma16(float* c, const uint32_t* a, const uint32_t* b) {
    asm volatile(
        "mma.sync.aligned.m16n8k16.row.col.f32.f16.f16.f32 "
        "{%0,%1,%2,%3}, {%4,%5,%6,%7}, {%8,%9}, {%0,%1,%2,%3};"
        : "+f"(c[0]), "+f"(c[1]), "+f"(c[2]), "+f"(c[3])
        : "r"(a[0]), "r"(a[1]), "r"(a[2]), "r"(a[3]), "r"(b[0]), "r"(b[1]));
}
__device__ __forceinline__ uint32_t h2u(float x, float y) {
    __half2 h = __floats2half2_rn(x, y);
    return *(uint32_t*)&h;
}
__device__ __forceinline__ float tanh_mufu(float x) {
    float y;
    asm("tanh.approx.f32 %0, %1;" : "=f"(y) : "f"(x));
    return y;
}
__device__ __forceinline__ float2 tanh2_f16(float ax, float ay) {
    __half2 hin = __floats2half2_rn(ax, ay);
    uint32_t ui = *(uint32_t*)&hin, uo;
    asm("tanh.approx.f16x2 %0, %1;" : "=r"(uo) : "r"(ui));
    __half2 ho = *(__half2*)&uo;
    return __half22float2(ho);
}
__device__ __forceinline__ unsigned ldflag(const unsigned* p) {
    unsigned v;
    asm volatile("ld.global.cg.u32 %0, [%1];" : "=r"(v) : "l"(p) : "memory");
    return v;
}

// ---------------------------------------------------------------------------
__global__ void init_kernel() {
    int i = blockIdx.x * blockDim.x + threadIdx.x;
    if (i < 64 * 512)   d_hf[0][i] = 0u;
    if (i < SRCLEN * 8) d_bar8[i]  = 0u;
}
__global__ void conv_emb_kernel(const float* __restrict__ emb) {
    size_t i = ((size_t)blockIdx.x * blockDim.x + threadIdx.x) * 8;
    float4 a = *(const float4*)(emb + i);
    float4 b = *(const float4*)(emb + i + 4);
    uint4 o = make_uint4(h2u(a.x, a.y), h2u(a.z, a.w), h2u(b.x, b.y), h2u(b.z, b.w));
    *(uint4*)(d_emb16 + i) = o;
}
__global__ void conv_wx_kernel(const float* __restrict__ Wx) {
    size_t i = ((size_t)blockIdx.x * blockDim.x + threadIdx.x) * 8;
    int n  = (int)(i >> 9);
    int k0 = (int)(i & 511);
    float4 a = *(const float4*)(Wx + i);
    float4 b = *(const float4*)(Wx + i + 4);
    unsigned base = (unsigned)((n >> 3) * 2048 + (k0 >> 4) * 64
                               + (n & 7) * 8 + ((k0 & 15) >> 3));
    d_wxf[base + 0] = h2u(a.x, a.y);
    d_wxf[base + 2] = h2u(a.z, a.w);
    d_wxf[base + 4] = h2u(b.x, b.y);
    d_wxf[base + 6] = h2u(b.z, b.w);
}

// ---------------------------------------------------------------------------
// Gather: emb16[tok] rows -> A-fragment layout d_af, one 64-row block per CTA.
// Smem transpose with XOR swizzle; writes out coalesced STG.128.
// ---------------------------------------------------------------------------
#define SWZ(w) ((w) ^ ((((w) >> 6) & 7) << 2))

__global__ void __launch_bounds__(256) gather_kernel(const int* __restrict__ src) {
    __shared__ unsigned s[4096];
    __shared__ int tok[64];
    const int tid = threadIdx.x;
    const int blk = blockIdx.x;                 // 64-row block = m-rows blk*64..+63
    if (tid < 64) tok[tid] = src[tid * SRCLEN + blk];   // m=blk*64+r: b=r, t=blk
    __syncthreads();

    unsigned* outb = d_af + (size_t)blk * AB_WORDS;
    const int r  = tid >> 2;                    // row within block
    const int qq = tid & 3;

    for (int grp = 0; grp < 4; grp++) {         // 8 kt per group
        if (grp) __syncthreads();
#pragma unroll
        for (int it = 0; it < 4; it++) {
            int q = qq * 4 + it;                // uint4 (8 halves) idx in group
            uint4 v = __ldg((const uint4*)(d_emb16 + (size_t)tok[r] * EMBED
                                           + grp * 128 + q * 8));
            int base = (q >> 1) * 512 + (r & 7) * 64 + ((r >> 3) << 1) + (q & 1);
            s[SWZ(base)]      = v.x;            // tg=0
            s[SWZ(base + 16)] = v.y;            // tg=1
            s[SWZ(base + 32)] = v.z;            // tg=2
            s[SWZ(base + 48)] = v.w;            // tg=3
        }
        __syncthreads();
#pragma unroll
        for (int it = 0; it < 4; it++) {
            int w4 = (tid + it * 256) * 4;
            *(uint4*)&outb[grp * 4096 + w4] = *(const uint4*)&s[SWZ(w4)];
        }
    }
}

// ---------------------------------------------------------------------------
// x_proj (fp16 mma), R16: fully smem-free. A and B fragments straight from
// gmem (L1/L2-cached), zero __syncthreads, per kt: 4 LDG.128 + 4 LDG.64 + 16 mma.
// ---------------------------------------------------------------------------
__global__ void __launch_bounds__(256, 2) xproj_kernel(const float* __restrict__ bx)
{
    const int tid  = threadIdx.x;
    const int lane = tid & 31;
    const int warp = tid >> 5;
    const int wm   = warp & 1;
    const int wn   = warp >> 1;
    const int g    = lane >> 2;
    const int tg   = lane & 3;
    const int bm0  = blockIdx.x * 128;          // m fast-varying
    const int bn0  = blockIdx.y * 128;

    // A fragment base for this warp's 64-row block
    const unsigned* ab = d_af + (size_t)(blockIdx.x * 2 + wm) * AB_WORDS
                         + g * 64 + tg * 16;
    // B fragment bases per nt
    unsigned gbase[4];
#pragma unroll
    for (int nt = 0; nt < 4; nt++)
        gbase[nt] = (unsigned)(((bn0 >> 3) + wn * 4 + nt) * 2048 + g * 8 + tg * 2);

    float acc[4][4][4];
#pragma unroll
    for (int mt = 0; mt < 4; mt++)
#pragma unroll
        for (int nt = 0; nt < 4; nt++)
#pragma unroll
            for (int r = 0; r < 4; r++) acc[mt][nt][r] = 0.0f;

#pragma unroll 4
    for (int kt = 0; kt < 32; kt++) {
        uint4 u0 = __ldg((const uint4*)&ab[kt * 512 + 0]);
        uint4 u1 = __ldg((const uint4*)&ab[kt * 512 + 4]);
        uint4 u2 = __ldg((const uint4*)&ab[kt * 512 + 8]);
        uint4 u3 = __ldg((const uint4*)&ab[kt * 512 + 12]);
        uint32_t af[4][4] = {
            {u0.x, u0.z, u0.y, u0.w}, {u1.x, u1.z, u1.y, u1.w},
            {u2.x, u2.z, u2.y, u2.w}, {u3.x, u3.z, u3.y, u3.w}};
        uint32_t bf[4][2];
#pragma unroll
        for (int nt = 0; nt < 4; nt++) {
            uint2 u = __ldg((const uint2*)&d_wxf[gbase[nt] + kt * 64]);
            bf[nt][0] = u.x; bf[nt][1] = u.y;
        }
#pragma unroll
        for (int mt = 0; mt < 4; mt++)
#pragma unroll
            for (int nt = 0; nt < 4; nt++)
                mma16(acc[mt][nt], af[mt], bf[nt]);
    }

    // epilogue: + bias, fp16 out
#pragma unroll
    for (int nt = 0; nt < 4; nt++) {
        int col = bn0 + wn * 32 + nt * 8 + tg * 2;
        float b0 = __ldg(bx + col);
        float b1 = __ldg(bx + col + 1);
#pragma unroll
        for (int mt = 0; mt < 4; mt++)
#pragma unroll
            for (int rr = 0; rr < 2; rr++) {
                int m = bm0 + wm * 64 + mt * 16 + rr * 8 + g;
                *(uint32_t*)(d_xp16 + (size_t)m * G4 + col) =
                    h2u(acc[mt][nt][rr * 2] + b0, acc[mt][nt][rr * 2 + 1] + b1);
            }
    }
}

// ---------------------------------------------------------------------------
// Recurrence (fp16 mma): frozen R14/R15 (quarter-gated start, proven).
// ---------------------------------------------------------------------------
#define PSTR 40
#define LSTM_SMEM_WORDS (16384 + 5 * 64 * PSTR)    // 29184 words = 116736 B

__global__ void __launch_bounds__(256, 1) lstm_kernel(
    const float* __restrict__ Wh, float* __restrict__ out)
{
    extern __shared__ float lsm[];
    uint32_t* Bs  = (uint32_t*)lsm;                 // 16384 words (64 KB)
    float*    psm = lsm + 16384;                    // [5][64][PSTR]

    const int tid  = threadIdx.x;
    const int lane = tid & 31;
    const int warp = tid >> 5;
    const int cta  = blockIdx.x;
    const int wm   = warp & 1;
    const int kh   = warp >> 1;
    const int g    = lane >> 2;
    const int tg   = lane & 3;

    // One-time: Wh slice -> fp16 B-fragment smem
    for (int i = tid; i < 32 * HIDDEN; i += 256) {
        int lc = i >> 10;
        int k  = i & 1023;
        int grow = (lc >> 3) * HIDDEN + cta * 8 + (lc & 7);
        float w = __ldg(Wh + (size_t)grow * HIDDEN + k);
        int kl = k & 15;
        int word = (k >> 4) * 256 + lc * 8 + ((kl & 7) >> 1) * 2 + (kl >> 3);
        ((__half*)Bs)[word * 2 + (k & 1)] = __float2half_rn(w);
    }
    __syncthreads();

    const int eb = tid >> 2;        // epilogue batch row
    const int eu = tid & 3;         // epilogue col-pair (j = 2eu, 2eu+1)
    float cst0 = 0.0f, cst1 = 0.0f;

    const int aoff  = (wm * 32 + g) * 8 + tg * 2;
    const int hword = (cta >> 1) * 512 + eb * 8 + eu * 2 + (cta & 1);

    for (int t = 0; t < SRCLEN; t++) {
        // xproj gates (fp16) -> registers; independent of h, overlaps the spin
        uint4 xu = __ldg((const uint4*)(d_xp16 + ((size_t)t * BATCH + eb) * G4
                                        + eu * HIDDEN + cta * 8));
        // quarter gate: this warp's K quarter (counters 2kh, 2kh+1) published
        if (t > 0) {
            bool ok;
            do {
                unsigned v = (lane < 2)
                    ? ldflag(&d_bar8[(t - 1) * 8 + kh * 2 + lane]) : 16u;
                ok = (v >= 16u);
            } while (!__all_sync(0xFFFFFFFFu, ok));
            __threadfence();   // acquire
        }

        float acc[2][4][4];
#pragma unroll
        for (int mt = 0; mt < 2; mt++)
#pragma unroll
            for (int nt = 0; nt < 4; nt++)
#pragma unroll
                for (int r = 0; r < 4; r++) acc[mt][nt][r] = 0.0f;

        const unsigned* hb = d_hf[t & 1];

#pragma unroll 8
        for (int ki = 0; ki < 16; ki++) {
            const int kt = kh * 16 + ki;
            const int kb = kt * 512;
            uint2 u00 = __ldcg((const uint2*)&hb[kb + aoff]);
            uint2 u01 = __ldcg((const uint2*)&hb[kb + aoff + 64]);
            uint2 u10 = __ldcg((const uint2*)&hb[kb + aoff + 128]);
            uint2 u11 = __ldcg((const uint2*)&hb[kb + aoff + 192]);
            uint32_t a0[4] = {u00.x, u01.x, u00.y, u01.y};
            uint32_t a1[4] = {u10.x, u11.x, u10.y, u11.y};
            const uint32_t* bp = Bs + kt * 256;
            uint32_t bf[4][2];
#pragma unroll
            for (int nt = 0; nt < 4; nt++) {
                uint2 u = *(const uint2*)&bp[(nt * 8 + g) * 8 + tg * 2];
                bf[nt][0] = u.x; bf[nt][1] = u.y;
            }
#pragma unroll
            for (int nt = 0; nt < 4; nt++) {
                mma16(acc[0][nt], a0, bf[nt]);
                mma16(acc[1][nt], a1, bf[nt]);
            }
        }

        // all warps publish partials; x (fp16->fp32) -> psm[4]
        {
            float* pp = psm + kh * (64 * PSTR);
#pragma unroll
            for (int mt = 0; mt < 2; mt++)
#pragma unroll
                for (int rr = 0; rr < 2; rr++) {
                    int row = wm * 32 + mt * 16 + rr * 8 + g;
#pragma unroll
                    for (int nt = 0; nt < 4; nt++)
                        *(float2*)&pp[row * PSTR + nt * 8 + tg * 2] =
                            make_float2(acc[mt][nt][rr * 2], acc[mt][nt][rr * 2 + 1]);
                }
            float* xd = psm + 4 * (64 * PSTR) + eb * PSTR + eu * 8;
            float2 x0 = __half22float2(*(__half2*)&xu.x);
            float2 x1 = __half22float2(*(__half2*)&xu.y);
            float2 x2 = __half22float2(*(__half2*)&xu.z);
            float2 x3 = __half22float2(*(__half2*)&xu.w);
            *(float4*)xd       = make_float4(x0.x, x0.y, x1.x, x1.y);
            *(float4*)(xd + 4) = make_float4(x2.x, x2.y, x3.x, x3.y);
        }
        __syncthreads();   // joins all 4 quarters' gates -> global WAR cover

        // epilogue: every thread handles (eb, j = 2eu, 2eu+1)
        {
            float2 gv[4];
#pragma unroll
            for (int gg = 0; gg < 4; gg++) {
                float2 s = make_float2(0.0f, 0.0f);
#pragma unroll
                for (int p = 0; p < 5; p++) {
                    float2 q = *(const float2*)&psm[p * (64 * PSTR)
                                + eb * PSTR + gg * 8 + eu * 2];
                    s.x += q.x; s.y += q.y;
                }
                gv[gg] = s;
            }
            float2 ti = tanh2_f16(0.5f * gv[0].x, 0.5f * gv[0].y);
            float2 tf = tanh2_f16(0.5f * gv[1].x, 0.5f * gv[1].y);
            float2 to = tanh2_f16(0.5f * gv[2].x, 0.5f * gv[2].y);
            float2 tgg = tanh2_f16(gv[3].x, gv[3].y);
            float ig0 = fmaf(0.5f, ti.x, 0.5f), ig1 = fmaf(0.5f, ti.y, 0.5f);
            float fg0 = fmaf(0.5f, tf.x, 0.5f), fg1 = fmaf(0.5f, tf.y, 0.5f);
            float og0 = fmaf(0.5f, to.x, 0.5f), og1 = fmaf(0.5f, to.y, 0.5f);

            float c0 = fg0 * cst0 + ig0 * tgg.x;  cst0 = c0;
            float c1 = fg1 * cst1 + ig1 * tgg.y;  cst1 = c1;
            float h0 = og0 * tanh_mufu(c0);
            float h1 = og1 * tanh_mufu(c1);

            __stcg(&d_hf[(t + 1) & 1][hword], h2u(h0, h1));
            if (t == SRCLEN - 1) {
                int col = cta * 8 + eu * 2;
                *(float2*)(out + eb * HIDDEN + col) = make_float2(h0, h1);
                *(float2*)(out + BATCH * HIDDEN + eb * HIDDEN + col) =
                    make_float2(c0, c1);
            }
        }

        // arrival: h(t+1) writes done CTA-wide, then one atomic to group cta>>4
        __syncthreads();
        if (tid == 0) {
            __threadfence();
            atomicAdd(&d_bar8[t * 8 + (cta >> 4)], 1u);
        }
    }
}

// ---------------------------------------------------------------------------
extern "C" void kernel_launch(void* const* d_in, const int* in_sizes, int n_in,
                              void* d_out, int out_size)
{
    const int*   src = (const int*)d_in[0];
    const float* emb = (const float*)d_in[1];
    const float* Wx  = (const float*)d_in[2];
    const float* bx  = (const float*)d_in[3];
    const float* Wh  = (const float*)d_in[4];
    float*       out = (float*)d_out;

    init_kernel<<<128, 256>>>();
    conv_emb_kernel<<<(VOCAB * EMBED / 8) / 256, 256>>>(emb);
    conv_wx_kernel<<<(G4 * EMBED / 8) / 256, 256>>>(Wx);
    gather_kernel<<<1024, 256>>>(src);

    xproj_kernel<<<dim3((SRCLEN * BATCH) / 128, G4 / 128), 256>>>(bx);

    cudaFuncSetAttribute(lstm_kernel, cudaFuncAttributeMaxDynamicSharedMemorySize,
                         LSTM_SMEM_WORDS * 4);
    lstm_kernel<<<NCTA, 256, LSTM_SMEM_WORDS * 4>>>(Wh, out);
}